// round 7
// baseline (speedup 1.0000x reference)
#include <cuda_runtime.h>
#include <cuda_bf16.h>
#include <cstdint>

#define N_NODES 50000
#define N_EDGES 500000
#define HID 128
#define OUTD 64

// ---------------- scratch (device globals; no runtime allocation) ----------
__device__ float g_agg[N_NODES * HID];
__device__ float g_h1[N_NODES * HID];
__device__ float g_h2[N_NODES * HID];
__device__ int   g_deg[N_NODES];
__device__ int   g_start[N_NODES];
__device__ int   g_cursor[N_NODES];
__device__ int   g_csr[N_EDGES];
__device__ int   g_tick;
__device__ int   g_run;

// ---------------- CSR build -------------------------------------------------
__global__ void k_zero_deg() {
    int i = blockIdx.x * blockDim.x + threadIdx.x;
    if (i < N_NODES) g_deg[i] = 0;
    if (i == 0) { g_tick = 0; g_run = 0; }
}

__global__ void k_count(const int* __restrict__ ei) {
    int e = blockIdx.x * blockDim.x + threadIdx.x;
    if (e < N_EDGES) atomicAdd(&g_deg[ei[N_EDGES + e]], 1);
}

// single-kernel chained exclusive scan: 13 blocks x 1024 threads x 4 elems
#define SCAN_BLOCKS 13
#define SCAN_CHUNK 4096

__global__ __launch_bounds__(1024)
void k_scan_fused() {
    __shared__ int sh[1024];
    __shared__ int s_off;
    int tid = threadIdx.x;
    int base = blockIdx.x * SCAN_CHUNK + tid * 4;

    int v0 = 0, v1 = 0, v2 = 0, v3 = 0;
    if (base + 3 < N_NODES) {
        int4 q = *(const int4*)(g_deg + base);
        v0 = q.x; v1 = q.y; v2 = q.z; v3 = q.w;
    } else {
        if (base + 0 < N_NODES) v0 = g_deg[base + 0];
        if (base + 1 < N_NODES) v1 = g_deg[base + 1];
        if (base + 2 < N_NODES) v2 = g_deg[base + 2];
        if (base + 3 < N_NODES) v3 = g_deg[base + 3];
    }
    int t1 = v0 + v1, t2 = t1 + v2, tsum = t2 + v3;
    sh[tid] = tsum;
    __syncthreads();
    for (int off = 1; off < 1024; off <<= 1) {
        int t = (tid >= off) ? sh[tid - off] : 0;
        __syncthreads();
        sh[tid] += t;
        __syncthreads();
    }
    int excl = sh[tid] - tsum;
    int total = sh[1023];

    if (tid == 0) {
        while (atomicAdd(&g_tick, 0) != (int)blockIdx.x) { }
        s_off = g_run;
        g_run = s_off + total;
        __threadfence();
        atomicExch(&g_tick, (int)blockIdx.x + 1);
    }
    __syncthreads();

    int off0 = s_off + excl;
    if (base + 3 < N_NODES) {
        int4 s;
        s.x = off0; s.y = off0 + v0; s.z = off0 + t1; s.w = off0 + t2;
        *(int4*)(g_start + base) = s;
        *(int4*)(g_cursor + base) = s;
    } else {
        if (base + 0 < N_NODES) { g_start[base + 0] = off0;      g_cursor[base + 0] = off0; }
        if (base + 1 < N_NODES) { g_start[base + 1] = off0 + v0; g_cursor[base + 1] = off0 + v0; }
        if (base + 2 < N_NODES) { g_start[base + 2] = off0 + t1; g_cursor[base + 2] = off0 + t1; }
        if (base + 3 < N_NODES) { g_start[base + 3] = off0 + t2; g_cursor[base + 3] = off0 + t2; }
    }
}

__global__ void k_fill(const int* __restrict__ ei) {
    int e = blockIdx.x * blockDim.x + threadIdx.x;
    if (e < N_EDGES) {
        int dst = ei[N_EDGES + e];
        int p = atomicAdd(&g_cursor[dst], 1);
        g_csr[p] = ei[e];
    }
}

// ---------------- mean aggregation (pull, one warp per node, 128-wide) ------
__global__ void k_aggregate(const float* __restrict__ hin) {
    int gw = (blockIdx.x * blockDim.x + threadIdx.x) >> 5;
    int lane = threadIdx.x & 31;
    if (gw >= N_NODES) return;

    int s = g_start[gw];
    int d = g_deg[gw];
    const float* base = hin + lane * 4;

    float4 acc = make_float4(0.f, 0.f, 0.f, 0.f);
    int j = 0;
    for (; j + 4 <= d; j += 4) {
        int s0 = g_csr[s + j + 0];
        int s1 = g_csr[s + j + 1];
        int s2 = g_csr[s + j + 2];
        int s3 = g_csr[s + j + 3];
        float4 v0 = *(const float4*)(base + s0 * HID);
        float4 v1 = *(const float4*)(base + s1 * HID);
        float4 v2 = *(const float4*)(base + s2 * HID);
        float4 v3 = *(const float4*)(base + s3 * HID);
        acc.x += v0.x + v1.x + v2.x + v3.x;
        acc.y += v0.y + v1.y + v2.y + v3.y;
        acc.z += v0.z + v1.z + v2.z + v3.z;
        acc.w += v0.w + v1.w + v2.w + v3.w;
    }
    for (; j < d; j++) {
        int s0 = g_csr[s + j];
        float4 v0 = *(const float4*)(base + s0 * HID);
        acc.x += v0.x; acc.y += v0.y; acc.z += v0.z; acc.w += v0.w;
    }
    float inv = (d > 0) ? (1.0f / (float)d) : 0.0f;
    float4 o;
    o.x = acc.x * inv; o.y = acc.y * inv; o.z = acc.z * inv; o.w = acc.w * inv;
    *(float4*)(g_agg + gw * HID + lane * 4) = o;
}

// ---- layer-3 epilogue: out_i = mean_j P_j + R_i (PR = [P|R], 128 wide) -----
__global__ void k_agg_add(const float* __restrict__ PR, float* __restrict__ out) {
    int gw = (blockIdx.x * blockDim.x + threadIdx.x) >> 5;
    int lane = threadIdx.x & 31;
    if (gw >= N_NODES) return;

    int s = g_start[gw];
    int d = g_deg[gw];
    const float* base = PR + lane * 2;

    float2 acc = make_float2(0.f, 0.f);
    int j = 0;
    for (; j + 4 <= d; j += 4) {
        int s0 = g_csr[s + j + 0];
        int s1 = g_csr[s + j + 1];
        int s2 = g_csr[s + j + 2];
        int s3 = g_csr[s + j + 3];
        float2 v0 = *(const float2*)(base + s0 * HID);
        float2 v1 = *(const float2*)(base + s1 * HID);
        float2 v2 = *(const float2*)(base + s2 * HID);
        float2 v3 = *(const float2*)(base + s3 * HID);
        acc.x += v0.x + v1.x + v2.x + v3.x;
        acc.y += v0.y + v1.y + v2.y + v3.y;
    }
    for (; j < d; j++) {
        int s0 = g_csr[s + j];
        float2 v0 = *(const float2*)(base + s0 * HID);
        acc.x += v0.x; acc.y += v0.y;
    }
    float inv = (d > 0) ? (1.0f / (float)d) : 0.0f;
    float2 r = *(const float2*)(PR + gw * HID + 64 + lane * 2);
    float2 o;
    o.x = acc.x * inv + r.x;
    o.y = acc.y * inv + r.y;
    *(float2*)(out + gw * OUTD + lane * 2) = o;
}

// ---------------- tf32 mma.sync GEMM ----------------------------------------
// D[128 rows, 128 cols] = Acat[128, K] @ Wcat[K, 128]  (+bias, +relu)
// MODE 0: K=256, Acat=[A1|A2], Wcat=[W1;W2] (each 128x128). out += bias, relu.
// MODE 1: K=128, Acat=A1, Wcat=[W3l|W3r] (each 128x64).
//         out[:,c] += (c>=64 ? bias[c-64] : 0), no relu.
// 256 threads = 8 warps; warp w owns rows [(w>>1)*32,+32), cols [(w&1)*64,+64).
// Fragment-order SMEM staging: mma operand loads are conflict-free LDS.128;
// staging global loads are float4 (LDG.128).
__device__ __forceinline__ uint32_t f2tf32(float v) {
    uint32_t t;
    asm("cvt.rn.tf32.f32 %0, %1;" : "=r"(t) : "f"(v));
    return t;
}

__device__ __forceinline__ void mma_tf32(float* c, const uint32_t* a,
                                         uint32_t b0, uint32_t b1) {
    asm volatile(
        "mma.sync.aligned.m16n8k8.row.col.f32.tf32.tf32.f32 "
        "{%0,%1,%2,%3}, {%4,%5,%6,%7}, {%8,%9}, {%0,%1,%2,%3};"
        : "+f"(c[0]), "+f"(c[1]), "+f"(c[2]), "+f"(c[3])
        : "r"(a[0]), "r"(a[1]), "r"(a[2]), "r"(a[3]), "r"(b0), "r"(b1));
}

template <int MODE>
__global__ __launch_bounds__(256)
void gemm_mma(const float* __restrict__ A1, const float* __restrict__ A2,
              const float* __restrict__ W1, const float* __restrict__ W2,
              const float* __restrict__ bias, float* __restrict__ out) {
    __shared__ uint32_t sA[4096];
    __shared__ uint32_t sB[4096];

    const int tid = threadIdx.x;
    const int warp = tid >> 5;
    const int lane = tid & 31;
    const int rs4 = warp >> 1;
    const int cs2 = warp & 1;
    const int row0 = blockIdx.x * 128;

    float acc[2][8][4];
#pragma unroll
    for (int m = 0; m < 2; m++)
#pragma unroll
        for (int t = 0; t < 8; t++)
#pragma unroll
            for (int q = 0; q < 4; q++) acc[m][t][q] = 0.f;

    const int KB = (MODE == 0) ? 8 : 4;
    for (int kb = 0; kb < KB; kb++) {
        const float* Asrc = (MODE == 0 && kb >= 4) ? A2 : A1;
        const int kbase = (MODE == 0) ? ((kb & 3) * 32) : (kb * 32);
        // ---- stage A tile [128 x 32] via float4 loads ----
#pragma unroll
        for (int l = 0; l < 4; l++) {
            int idx4 = tid + l * 256;            // 0..1023 float4 slots
            int r = idx4 >> 3;
            int kl0 = (idx4 & 7) * 4;
            int rg = row0 + r;
            if (rg >= N_NODES) rg = N_NODES - 1;
            float4 f = *(const float4*)(Asrc + (size_t)rg * HID + kbase + kl0);
            int ks = kl0 >> 3, kkhi = (kl0 >> 2) & 1;
            int rr = r & 31, rsd = r >> 5;
            int m = rr >> 4, r16 = rr & 15;
            int w = m * 4 + kkhi * 2 + (r16 >> 3);
            int lnb = (r16 & 7) * 4;
            uint32_t* p = &sA[(((ks * 4 + rsd) * 2 + (w >> 2)) * 32 + lnb) * 4 + (w & 3)];
            p[0]  = f2tf32(f.x);
            p[4]  = f2tf32(f.y);
            p[8]  = f2tf32(f.z);
            p[12] = f2tf32(f.w);
        }
        // ---- stage B tile [32 x 128] via float4 loads ----
#pragma unroll
        for (int l = 0; l < 4; l++) {
            int idx4 = tid + l * 256;
            int n0 = (idx4 & 31) * 4;
            int kl = idx4 >> 5;                  // 0..31
            float4 f;
            if (MODE == 0) {
                const float* Ws = (kb < 4) ? W1 : W2;
                f = *(const float4*)(Ws + ((kb & 3) * 32 + kl) * 128 + n0);
            } else {
                int kg = kb * 32 + kl;
                f = (n0 < 64) ? *(const float4*)(W1 + kg * 64 + n0)
                              : *(const float4*)(W2 + kg * 64 + (n0 - 64));
            }
            int ks = kl >> 3, kk = kl & 7;
            int c2 = n0 >> 6, nn0 = n0 & 63;
            int w = (nn0 >> 3) * 2 + (kk >> 2);
            int ln0 = (nn0 & 7) * 4 + (kk & 3);
            uint32_t* p = &sB[(((ks * 2 + c2) * 4 + (w >> 2)) * 32 + ln0) * 4 + (w & 3)];
            p[0]  = f2tf32(f.x);
            p[16] = f2tf32(f.y);
            p[32] = f2tf32(f.z);
            p[48] = f2tf32(f.w);
        }
        __syncthreads();

        // ---- compute: 4 k-steps of m16n8k8 ----
#pragma unroll
        for (int ks = 0; ks < 4; ks++) {
            uint32_t a[8];
            uint32_t b[16];
            const uint4* pa = (const uint4*)sA;
            const uint4* pb = (const uint4*)sB;
            uint4 a0 = pa[((ks * 4 + rs4) * 2 + 0) * 32 + lane];
            uint4 a1 = pa[((ks * 4 + rs4) * 2 + 1) * 32 + lane];
            a[0] = a0.x; a[1] = a0.y; a[2] = a0.z; a[3] = a0.w;
            a[4] = a1.x; a[5] = a1.y; a[6] = a1.z; a[7] = a1.w;
#pragma unroll
            for (int h = 0; h < 4; h++) {
                uint4 bv = pb[((ks * 2 + cs2) * 4 + h) * 32 + lane];
                b[h * 4 + 0] = bv.x; b[h * 4 + 1] = bv.y;
                b[h * 4 + 2] = bv.z; b[h * 4 + 3] = bv.w;
            }
#pragma unroll
            for (int m = 0; m < 2; m++)
#pragma unroll
                for (int t = 0; t < 8; t++)
                    mma_tf32(acc[m][t], a + m * 4, b[2 * t], b[2 * t + 1]);
        }
        __syncthreads();
    }

    // ---- epilogue: bias (+relu), float2 stores ----
#pragma unroll
    for (int m = 0; m < 2; m++) {
#pragma unroll
        for (int q2 = 0; q2 < 2; q2++) {
            int row = row0 + rs4 * 32 + m * 16 + q2 * 8 + (lane >> 2);
            if (row < N_NODES) {
#pragma unroll
                for (int t = 0; t < 8; t++) {
                    int col = cs2 * 64 + t * 8 + (lane & 3) * 2;
                    float2 v;
                    v.x = acc[m][t][q2 * 2 + 0];
                    v.y = acc[m][t][q2 * 2 + 1];
                    if (MODE == 0) {
                        v.x += bias[col];
                        v.y += bias[col + 1];
                        v.x = fmaxf(v.x, 0.f);
                        v.y = fmaxf(v.y, 0.f);
                    } else {
                        if (col >= 64) {
                            v.x += bias[col - 64];
                            v.y += bias[col - 63];
                        }
                    }
                    *(float2*)(out + (size_t)row * 128 + col) = v;
                }
            }
        }
    }
}

// ---------------- launch ----------------------------------------------------
extern "C" void kernel_launch(void* const* d_in, const int* in_sizes, int n_in,
                              void* d_out, int out_size) {
    const float* x   = (const float*)d_in[0];
    const int*   ei  = (const int*)d_in[1];
    const float* W1l = (const float*)d_in[2];
    const float* W1r = (const float*)d_in[3];
    const float* b1  = (const float*)d_in[4];
    const float* W2l = (const float*)d_in[5];
    const float* W2r = (const float*)d_in[6];
    const float* b2  = (const float*)d_in[7];
    const float* W3l = (const float*)d_in[8];
    const float* W3r = (const float*)d_in[9];
    const float* b3  = (const float*)d_in[10];
    float* out = (float*)d_out;

    float *agg, *h1, *h2;
    cudaGetSymbolAddress((void**)&agg, g_agg);
    cudaGetSymbolAddress((void**)&h1, g_h1);
    cudaGetSymbolAddress((void**)&h2, g_h2);

    const int NB_N = (N_NODES + 255) / 256;
    const int NB_E = (N_EDGES + 255) / 256;
    const int NB_AGG = (N_NODES + 7) / 8;
    const int NB_GEMM = (N_NODES + 127) / 128;    // 391

    // CSR build
    k_zero_deg<<<NB_N, 256>>>();
    k_count<<<NB_E, 256>>>(ei);
    k_scan_fused<<<SCAN_BLOCKS, 1024>>>();
    k_fill<<<NB_E, 256>>>(ei);

    // Layer 1: h1 = relu(agg(x)@W1l + x@W1r + b1)
    k_aggregate<<<NB_AGG, 256>>>(x);
    gemm_mma<0><<<NB_GEMM, 256>>>(agg, x, W1l, W1r, b1, h1);
    // Layer 2
    k_aggregate<<<NB_AGG, 256>>>(h1);
    gemm_mma<0><<<NB_GEMM, 256>>>(agg, h1, W2l, W2r, b2, h2);
    // Layer 3 (post-aggregation by linearity): PR = h2 @ [W3l | W3r] (+b3 on R)
    gemm_mma<1><<<NB_GEMM, 256>>>(h2, h2, W3l, W3r, b3, agg);
    k_agg_add<<<NB_AGG, 256>>>(agg, out);
}

// round 11
// speedup vs baseline: 1.5367x; 1.5367x over previous
#include <cuda_runtime.h>
#include <cuda_bf16.h>
#include <cstdint>

#define N_NODES 50000
#define N_EDGES 500000
#define HID 128
#define OUTD 64

// ---------------- scratch (device globals; no runtime allocation) ----------
__device__ float g_agg[N_NODES * HID];
__device__ float g_h1[N_NODES * HID];
__device__ float g_h2[N_NODES * HID];
__device__ int   g_deg[N_NODES];
__device__ int   g_start[N_NODES];
__device__ int   g_cursor[N_NODES];
__device__ int   g_csr[N_EDGES];
__device__ int   g_bsum[64];

// ---------------- CSR build -------------------------------------------------
__global__ void k_zero_deg() {
    int i = blockIdx.x * blockDim.x + threadIdx.x;
    if (i < N_NODES) g_deg[i] = 0;
}

__global__ void k_count(const int* __restrict__ ei) {
    int e = blockIdx.x * blockDim.x + threadIdx.x;
    if (e < N_EDGES) atomicAdd(&g_deg[ei[N_EDGES + e]], 1);
}

__global__ void k_scan1() {
    __shared__ int sh[1024];
    int tid = threadIdx.x;
    int i = blockIdx.x * 1024 + tid;
    int v = (i < N_NODES) ? g_deg[i] : 0;
    sh[tid] = v;
    __syncthreads();
    for (int off = 1; off < 1024; off <<= 1) {
        int t = (tid >= off) ? sh[tid - off] : 0;
        __syncthreads();
        sh[tid] += t;
        __syncthreads();
    }
    if (i < N_NODES) g_start[i] = sh[tid] - v;   // exclusive
    if (tid == 1023) g_bsum[blockIdx.x] = sh[1023];
}

__global__ void k_scan2(int nb) {
    __shared__ int sh[64];
    int t = threadIdx.x;
    int v = (t < nb) ? g_bsum[t] : 0;
    sh[t] = v;
    __syncthreads();
    for (int off = 1; off < 64; off <<= 1) {
        int u = (t >= off) ? sh[t - off] : 0;
        __syncthreads();
        sh[t] += u;
        __syncthreads();
    }
    if (t < nb) g_bsum[t] = sh[t] - v;           // exclusive
}

__global__ void k_scan3() {
    int i = blockIdx.x * blockDim.x + threadIdx.x;
    if (i < N_NODES) {
        int s = g_start[i] + g_bsum[i >> 10];
        g_start[i] = s;
        g_cursor[i] = s;
    }
}

__global__ void k_fill(const int* __restrict__ ei) {
    int e = blockIdx.x * blockDim.x + threadIdx.x;
    if (e < N_EDGES) {
        int dst = ei[N_EDGES + e];
        int p = atomicAdd(&g_cursor[dst], 1);
        g_csr[p] = ei[e];
    }
}

// ---------------- mean aggregation (pull, one warp per node, 128-wide) ------
__global__ void k_aggregate(const float* __restrict__ hin) {
    int gw = (blockIdx.x * blockDim.x + threadIdx.x) >> 5;
    int lane = threadIdx.x & 31;
    if (gw >= N_NODES) return;

    int s = g_start[gw];
    int d = g_deg[gw];
    const float* base = hin + lane * 4;

    float4 acc = make_float4(0.f, 0.f, 0.f, 0.f);
    int j = 0;
    for (; j + 4 <= d; j += 4) {
        int s0 = g_csr[s + j + 0];
        int s1 = g_csr[s + j + 1];
        int s2 = g_csr[s + j + 2];
        int s3 = g_csr[s + j + 3];
        float4 v0 = *(const float4*)(base + s0 * HID);
        float4 v1 = *(const float4*)(base + s1 * HID);
        float4 v2 = *(const float4*)(base + s2 * HID);
        float4 v3 = *(const float4*)(base + s3 * HID);
        acc.x += v0.x + v1.x + v2.x + v3.x;
        acc.y += v0.y + v1.y + v2.y + v3.y;
        acc.z += v0.z + v1.z + v2.z + v3.z;
        acc.w += v0.w + v1.w + v2.w + v3.w;
    }
    for (; j < d; j++) {
        int s0 = g_csr[s + j];
        float4 v0 = *(const float4*)(base + s0 * HID);
        acc.x += v0.x; acc.y += v0.y; acc.z += v0.z; acc.w += v0.w;
    }
    float inv = (d > 0) ? (1.0f / (float)d) : 0.0f;
    float4 o;
    o.x = acc.x * inv; o.y = acc.y * inv; o.z = acc.z * inv; o.w = acc.w * inv;
    *(float4*)(g_agg + gw * HID + lane * 4) = o;
}

// ---- layer-3 epilogue: out_i = mean_j P_j + R_i (PR = [P|R], 128 wide) -----
__global__ void k_agg_add(const float* __restrict__ PR, float* __restrict__ out) {
    int gw = (blockIdx.x * blockDim.x + threadIdx.x) >> 5;
    int lane = threadIdx.x & 31;
    if (gw >= N_NODES) return;

    int s = g_start[gw];
    int d = g_deg[gw];
    const float* base = PR + lane * 2;

    float2 acc = make_float2(0.f, 0.f);
    int j = 0;
    for (; j + 4 <= d; j += 4) {
        int s0 = g_csr[s + j + 0];
        int s1 = g_csr[s + j + 1];
        int s2 = g_csr[s + j + 2];
        int s3 = g_csr[s + j + 3];
        float2 v0 = *(const float2*)(base + s0 * HID);
        float2 v1 = *(const float2*)(base + s1 * HID);
        float2 v2 = *(const float2*)(base + s2 * HID);
        float2 v3 = *(const float2*)(base + s3 * HID);
        acc.x += v0.x + v1.x + v2.x + v3.x;
        acc.y += v0.y + v1.y + v2.y + v3.y;
    }
    for (; j < d; j++) {
        int s0 = g_csr[s + j];
        float2 v0 = *(const float2*)(base + s0 * HID);
        acc.x += v0.x; acc.y += v0.y;
    }
    float inv = (d > 0) ? (1.0f / (float)d) : 0.0f;
    float2 r = *(const float2*)(PR + gw * HID + 64 + lane * 2);
    float2 o;
    o.x = acc.x * inv + r.x;
    o.y = acc.y * inv + r.y;
    *(float2*)(out + gw * OUTD + lane * 2) = o;
}

// ---------------- tf32 mma.sync GEMM ----------------------------------------
// D[128 rows, 128 cols] = Acat[128, K] @ Wcat[K, 128]  (+bias, +relu)
// MODE 0: K=256, Acat=[A1|A2], Wcat=[W1;W2] (each 128x128). out += bias, relu.
// MODE 1: K=128, Acat=A1, Wcat=[W3l|W3r] (each 128x64).
//         out[:,c] += (c>=64 ? bias[c-64] : 0), no relu.
// 256 threads = 8 warps; warp w owns rows [(w>>1)*32,+32), cols [(w&1)*64,+64).
// Fragment-order SMEM staging: mma operand loads are conflict-free LDS.128;
// staging global loads are float4 (LDG.128).
__device__ __forceinline__ uint32_t f2tf32(float v) {
    uint32_t t;
    asm("cvt.rn.tf32.f32 %0, %1;" : "=r"(t) : "f"(v));
    return t;
}

__device__ __forceinline__ void mma_tf32(float* c, const uint32_t* a,
                                         uint32_t b0, uint32_t b1) {
    asm volatile(
        "mma.sync.aligned.m16n8k8.row.col.f32.tf32.tf32.f32 "
        "{%0,%1,%2,%3}, {%4,%5,%6,%7}, {%8,%9}, {%0,%1,%2,%3};"
        : "+f"(c[0]), "+f"(c[1]), "+f"(c[2]), "+f"(c[3])
        : "r"(a[0]), "r"(a[1]), "r"(a[2]), "r"(a[3]), "r"(b0), "r"(b1));
}

template <int MODE>
__global__ __launch_bounds__(256)
void gemm_mma(const float* __restrict__ A1, const float* __restrict__ A2,
              const float* __restrict__ W1, const float* __restrict__ W2,
              const float* __restrict__ bias, float* __restrict__ out) {
    __shared__ uint32_t sA[4096];
    __shared__ uint32_t sB[4096];

    const int tid = threadIdx.x;
    const int warp = tid >> 5;
    const int lane = tid & 31;
    const int rs4 = warp >> 1;
    const int cs2 = warp & 1;
    const int row0 = blockIdx.x * 128;

    float acc[2][8][4];
#pragma unroll
    for (int m = 0; m < 2; m++)
#pragma unroll
        for (int t = 0; t < 8; t++)
#pragma unroll
            for (int q = 0; q < 4; q++) acc[m][t][q] = 0.f;

    const int KB = (MODE == 0) ? 8 : 4;
    for (int kb = 0; kb < KB; kb++) {
        const float* Asrc = (MODE == 0 && kb >= 4) ? A2 : A1;
        const int kbase = (MODE == 0) ? ((kb & 3) * 32) : (kb * 32);
        // ---- stage A tile [128 x 32] via float4 loads ----
#pragma unroll
        for (int l = 0; l < 4; l++) {
            int idx4 = tid + l * 256;            // 0..1023 float4 slots
            int r = idx4 >> 3;
            int kl0 = (idx4 & 7) * 4;
            int rg = row0 + r;
            if (rg >= N_NODES) rg = N_NODES - 1;
            float4 f = *(const float4*)(Asrc + (size_t)rg * HID + kbase + kl0);
            int ks = kl0 >> 3, kkhi = (kl0 >> 2) & 1;
            int rr = r & 31, rsd = r >> 5;
            int m = rr >> 4, r16 = rr & 15;
            int w = m * 4 + kkhi * 2 + (r16 >> 3);
            int lnb = (r16 & 7) * 4;
            uint32_t* p = &sA[(((ks * 4 + rsd) * 2 + (w >> 2)) * 32 + lnb) * 4 + (w & 3)];
            p[0]  = f2tf32(f.x);
            p[4]  = f2tf32(f.y);
            p[8]  = f2tf32(f.z);
            p[12] = f2tf32(f.w);
        }
        // ---- stage B tile [32 x 128] via float4 loads ----
#pragma unroll
        for (int l = 0; l < 4; l++) {
            int idx4 = tid + l * 256;
            int n0 = (idx4 & 31) * 4;
            int kl = idx4 >> 5;                  // 0..31
            float4 f;
            if (MODE == 0) {
                const float* Ws = (kb < 4) ? W1 : W2;
                f = *(const float4*)(Ws + ((kb & 3) * 32 + kl) * 128 + n0);
            } else {
                int kg = kb * 32 + kl;
                f = (n0 < 64) ? *(const float4*)(W1 + kg * 64 + n0)
                              : *(const float4*)(W2 + kg * 64 + (n0 - 64));
            }
            int ks = kl >> 3, kk = kl & 7;
            int c2 = n0 >> 6, nn0 = n0 & 63;
            int w = (nn0 >> 3) * 2 + (kk >> 2);
            int ln0 = (nn0 & 7) * 4 + (kk & 3);
            uint32_t* p = &sB[(((ks * 2 + c2) * 4 + (w >> 2)) * 32 + ln0) * 4 + (w & 3)];
            p[0]  = f2tf32(f.x);
            p[16] = f2tf32(f.y);
            p[32] = f2tf32(f.z);
            p[48] = f2tf32(f.w);
        }
        __syncthreads();

        // ---- compute: 4 k-steps of m16n8k8 ----
#pragma unroll
        for (int ks = 0; ks < 4; ks++) {
            uint32_t a[8];
            uint32_t b[16];
            const uint4* pa = (const uint4*)sA;
            const uint4* pb = (const uint4*)sB;
            uint4 a0 = pa[((ks * 4 + rs4) * 2 + 0) * 32 + lane];
            uint4 a1 = pa[((ks * 4 + rs4) * 2 + 1) * 32 + lane];
            a[0] = a0.x; a[1] = a0.y; a[2] = a0.z; a[3] = a0.w;
            a[4] = a1.x; a[5] = a1.y; a[6] = a1.z; a[7] = a1.w;
#pragma unroll
            for (int h = 0; h < 4; h++) {
                uint4 bv = pb[((ks * 2 + cs2) * 4 + h) * 32 + lane];
                b[h * 4 + 0] = bv.x; b[h * 4 + 1] = bv.y;
                b[h * 4 + 2] = bv.z; b[h * 4 + 3] = bv.w;
            }
#pragma unroll
            for (int m = 0; m < 2; m++)
#pragma unroll
                for (int t = 0; t < 8; t++)
                    mma_tf32(acc[m][t], a + m * 4, b[2 * t], b[2 * t + 1]);
        }
        __syncthreads();
    }

    // ---- epilogue: bias (+relu), float2 stores ----
#pragma unroll
    for (int m = 0; m < 2; m++) {
#pragma unroll
        for (int q2 = 0; q2 < 2; q2++) {
            int row = row0 + rs4 * 32 + m * 16 + q2 * 8 + (lane >> 2);
            if (row < N_NODES) {
#pragma unroll
                for (int t = 0; t < 8; t++) {
                    int col = cs2 * 64 + t * 8 + (lane & 3) * 2;
                    float2 v;
                    v.x = acc[m][t][q2 * 2 + 0];
                    v.y = acc[m][t][q2 * 2 + 1];
                    if (MODE == 0) {
                        v.x += bias[col];
                        v.y += bias[col + 1];
                        v.x = fmaxf(v.x, 0.f);
                        v.y = fmaxf(v.y, 0.f);
                    } else {
                        if (col >= 64) {
                            v.x += bias[col - 64];
                            v.y += bias[col - 63];
                        }
                    }
                    *(float2*)(out + (size_t)row * 128 + col) = v;
                }
            }
        }
    }
}

// ---------------- launch ----------------------------------------------------
extern "C" void kernel_launch(void* const* d_in, const int* in_sizes, int n_in,
                              void* d_out, int out_size) {
    const float* x   = (const float*)d_in[0];
    const int*   ei  = (const int*)d_in[1];
    const float* W1l = (const float*)d_in[2];
    const float* W1r = (const float*)d_in[3];
    const float* b1  = (const float*)d_in[4];
    const float* W2l = (const float*)d_in[5];
    const float* W2r = (const float*)d_in[6];
    const float* b2  = (const float*)d_in[7];
    const float* W3l = (const float*)d_in[8];
    const float* W3r = (const float*)d_in[9];
    const float* b3  = (const float*)d_in[10];
    float* out = (float*)d_out;

    float *agg, *h1, *h2;
    cudaGetSymbolAddress((void**)&agg, g_agg);
    cudaGetSymbolAddress((void**)&h1, g_h1);
    cudaGetSymbolAddress((void**)&h2, g_h2);

    const int NB_N = (N_NODES + 255) / 256;
    const int NB_E = (N_EDGES + 255) / 256;
    const int NB_S = (N_NODES + 1023) / 1024;     // 49
    const int NB_AGG = (N_NODES + 7) / 8;
    const int NB_GEMM = (N_NODES + 127) / 128;    // 391

    // CSR build (R6 structure — measured good)
    k_zero_deg<<<NB_N, 256>>>();
    k_count<<<NB_E, 256>>>(ei);
    k_scan1<<<NB_S, 1024>>>();
    k_scan2<<<1, 64>>>(NB_S);
    k_scan3<<<NB_N, 256>>>();
    k_fill<<<NB_E, 256>>>(ei);

    // Layer 1: h1 = relu(agg(x)@W1l + x@W1r + b1)
    k_aggregate<<<NB_AGG, 256>>>(x);
    gemm_mma<0><<<NB_GEMM, 256>>>(agg, x, W1l, W1r, b1, h1);
    // Layer 2
    k_aggregate<<<NB_AGG, 256>>>(h1);
    gemm_mma<0><<<NB_GEMM, 256>>>(agg, h1, W2l, W2r, b2, h2);
    // Layer 3 (post-aggregation by linearity): PR = h2 @ [W3l | W3r] (+b3 on R)
    gemm_mma<1><<<NB_GEMM, 256>>>(h2, h2, W3l, W3r, b3, agg);
    k_agg_add<<<NB_AGG, 256>>>(agg, out);
}